// round 15
// baseline (speedup 1.0000x reference)
#include <cuda_runtime.h>
#include <cuda_fp16.h>

#define DIMF 1536
#define SEQ  1560
#define LKV  4680
#define NH   12
#define HD   128

// ---------------- device-global scratch (allocation-free) ----------------
__device__ float  g_q[SEQ * DIMF];            // fp32 q pre-norm
__device__ float  g_k[SEQ * DIMF];            // fp32 k pre-norm
__device__ __half g_xh[SEQ * DIMF];           // fp16 x
__device__ __half g_wt[3 * DIMF * DIMF];      // fp16 W^T qkv: [n 4608][k 1536]
__device__ __half g_wot[DIMF * DIMF];         // fp16 Wo^T: [n][k]
__device__ __half g_qh[NH * SEQ * HD];        // fp16 q per-head (RoPE'd, prescaled)
__device__ __half g_kh[NH * LKV * HD];        // fp16 logical K per-head
__device__ __half g_vh[NH * LKV * HD];        // fp16 logical V per-head
__device__ __half g_oh[SEQ * DIMF];           // fp16 attention output

__device__ __forceinline__ unsigned pk2(float a, float b) {
    __half2 h = __floats2half2_rn(a, b);
    return *reinterpret_cast<unsigned*>(&h);
}
__device__ __forceinline__ unsigned ex2h2(unsigned x) {
    unsigned r; asm("ex2.approx.f16x2 %0, %1;" : "=r"(r) : "r"(x)); return r;
}
__device__ __forceinline__ uint4 cvt8(float4 a, float4 b) {
    uint4 u;
    u.x = pk2(a.x, a.y); u.y = pk2(a.z, a.w);
    u.z = pk2(b.x, b.y); u.w = pk2(b.z, b.w);
    return u;
}
__device__ __forceinline__ void mma16(float* d, const unsigned* a, const unsigned* b) {
    asm volatile(
        "mma.sync.aligned.m16n8k16.row.col.f32.f16.f16.f32 "
        "{%0,%1,%2,%3},{%4,%5,%6,%7},{%8,%9},{%0,%1,%2,%3};"
        : "+f"(d[0]), "+f"(d[1]), "+f"(d[2]), "+f"(d[3])
        : "r"(a[0]), "r"(a[1]), "r"(a[2]), "r"(a[3]), "r"(b[0]), "r"(b[1]));
}
__device__ __forceinline__ void ldm4(unsigned* r, const void* p) {
    unsigned a = (unsigned)__cvta_generic_to_shared(p);
    asm volatile("ldmatrix.sync.aligned.m8n8.x4.shared.b16 {%0,%1,%2,%3},[%4];"
                 : "=r"(r[0]), "=r"(r[1]), "=r"(r[2]), "=r"(r[3]) : "r"(a));
}
__device__ __forceinline__ void ldm4t(unsigned* r, const void* p) {
    unsigned a = (unsigned)__cvta_generic_to_shared(p);
    asm volatile("ldmatrix.sync.aligned.m8n8.x4.trans.shared.b16 {%0,%1,%2,%3},[%4];"
                 : "=r"(r[0]), "=r"(r[1]), "=r"(r[2]), "=r"(r[3]) : "r"(a));
}
__device__ __forceinline__ void ldm2t(unsigned* r, const void* p) {
    unsigned a = (unsigned)__cvta_generic_to_shared(p);
    asm volatile("ldmatrix.sync.aligned.m8n8.x2.trans.shared.b16 {%0,%1},[%2];"
                 : "=r"(r[0]), "=r"(r[1]) : "r"(a));
}
__device__ __forceinline__ void cpa16(void* dst, const void* src) {
    unsigned d = (unsigned)__cvta_generic_to_shared(dst);
    asm volatile("cp.async.cg.shared.global [%0], [%1], 16;" :: "r"(d), "l"(src));
}

// ---------------------------------------------------------------------------
// fp32 -> fp16 bulk convert
// ---------------------------------------------------------------------------
__global__ void f2h(const float* __restrict__ in, __half* __restrict__ out, int n) {
    int i = (blockIdx.x * blockDim.x + threadIdx.x) * 8;
    if (i < n) {
        float4 a = *(const float4*)(in + i);
        float4 b = *(const float4*)(in + i + 4);
        *(uint4*)(out + i) = cvt8(a, b);
    }
}

// ---------------------------------------------------------------------------
// W [k][n] fp32 -> W^T [n][k] fp16, tiled transpose
// ---------------------------------------------------------------------------
__global__ __launch_bounds__(256) void wtrans(
    const float* __restrict__ s0, const float* __restrict__ s1,
    const float* __restrict__ s2, __half* __restrict__ wT)
{
    __shared__ float t[32][33];
    int bn = blockIdx.x * 32, bk = blockIdx.y * 32;
    int region = bn / DIMF;
    const float* src = region == 0 ? s0 : region == 1 ? s1 : s2;
    int ln = bn - region * DIMF;
    int tx = threadIdx.x, ty = threadIdx.y;
#pragma unroll
    for (int i = ty; i < 32; i += 8)
        t[i][tx] = src[(size_t)(bk + i) * DIMF + ln + tx];
    __syncthreads();
#pragma unroll
    for (int i = ty; i < 32; i += 8)
        wT[(size_t)(bn + i) * DIMF + bk + tx] = __float2half(t[tx][i]);
}

// ---------------------------------------------------------------------------
// cache rows -> per-head contiguous fp16 logical KV
// ---------------------------------------------------------------------------
__global__ __launch_bounds__(256) void cacheconv(
    const float* __restrict__ ck, const float* __restrict__ cv,
    __half* __restrict__ kh, __half* __restrict__ vh)
{
    int idx = blockIdx.x * 256 + threadIdx.x;
    if (idx >= 3120 * NH * 16) return;
    int d8 = (idx & 15) * 8;
    int jh = idx >> 4;
    int h = jh % NH;
    int j = jh / NH;
    int jj = j < 1560 ? j : j + 1560;
    size_t src = ((size_t)jj * NH + h) * HD + d8;
    size_t dst = ((size_t)h * LKV + j) * HD + d8;
    float4 a0 = *(const float4*)(ck + src);
    float4 a1 = *(const float4*)(ck + src + 4);
    *(uint4*)(kh + dst) = cvt8(a0, a1);
    float4 b0 = *(const float4*)(cv + src);
    float4 b1 = *(const float4*)(cv + src + 4);
    *(uint4*)(vh + dst) = cvt8(b0, b1);
}

// ---------------------------------------------------------------------------
// RMSNorm + RoPE (unchanged)
// ---------------------------------------------------------------------------
__global__ __launch_bounds__(256) void rmsrope(
    const float* __restrict__ qbuf, const float* __restrict__ kbuf,
    const float* __restrict__ gq, const float* __restrict__ gk,
    const float* __restrict__ fre, const float* __restrict__ fim,
    __half* __restrict__ qh, __half* __restrict__ kh)
{
    const int t = blockIdx.x;
    const bool isq = blockIdx.y == 0;
    const float* row = (isq ? qbuf : kbuf) + (size_t)t * DIMF;
    const float* g = isq ? gq : gk;
    const int tid = threadIdx.x;

    float ss = 0.f;
#pragma unroll
    for (int u = 0; u < 6; u++) { float v = row[tid + u * 256]; ss += v * v; }
#pragma unroll
    for (int off = 16; off; off >>= 1) ss += __shfl_xor_sync(0xffffffffu, ss, off);
    __shared__ float red[8];
    if ((tid & 31) == 0) red[tid >> 5] = ss;
    __syncthreads();
    float tot = red[0] + red[1] + red[2] + red[3] + red[4] + red[5] + red[6] + red[7];
    float r = rsqrtf(tot * (1.f / 1536.f) + 1e-6f);
    const float sc = isq ? 0.08838834764831845f * 1.4426950408889634f : 1.0f;

    const int wi = t % 52;
    const int hi = t / 52;
#pragma unroll
    for (int u = 0; u < 3; u++) {
        int p = tid + u * 256;
        int hh = p >> 6, c = p & 63;
        int d0 = hh * 128 + 2 * c;
        int frow = (c < 22) ? 3 : (c < 43) ? hi : wi;
        float cr = fre[frow * 64 + c], ci = fim[frow * 64 + c];
        float v0 = row[d0] * r * g[d0];
        float v1 = row[d0 + 1] * r * g[d0 + 1];
        float y0 = (v0 * cr - v1 * ci) * sc;
        float y1 = (v0 * ci + v1 * cr) * sc;
        __half* dst = isq ? qh + ((size_t)hh * SEQ + t) * HD + 2 * c
                          : kh + ((size_t)hh * LKV + 3120 + t) * HD + 2 * c;
        *(__half2*)dst = __floats2half2_rn(y0, y1);
    }
}

// ---------------------------------------------------------------------------
// GEMM (mma.sync): BM=BN=128, BK=32, 128 threads, warp tile 64x64.
// 3-stage cp.async pipeline (2 fetches in flight), ONE sync per k-iter,
// issue-before-compute. GAS=40 halfs = 80B row stride: 16B-aligned cp.async
// destinations AND conflict-free ldmatrix (80*r mod 128 covers all offsets).
// 61440 B smem -> 3 blocks/SM.
// ---------------------------------------------------------------------------
#define GAS 40                     // halfs per staged row (32 + 8 pad)
#define GSTA (128 * GAS * 2)       // bytes of A region per stage (10240)
#define GSTGB (2 * GSTA)           // stage bytes A+B (20480)
#define NKT 48                     // 1536 / 32

template <int MODE>
__global__ __launch_bounds__(128, 3) void gemm_h(
    const __half* __restrict__ A, const __half* __restrict__ WT,
    const float* __restrict__ b0, const float* __restrict__ b1,
    const float* __restrict__ b2,
    float* __restrict__ o0, float* __restrict__ o1, __half* __restrict__ o2)
{
    extern __shared__ char gsm[];
    const int bm = blockIdx.x * 128, bn = blockIdx.y * 128;
    const int tid = threadIdx.x, lane = tid & 31, warp = tid >> 5;
    const int wm = (warp >> 1) * 64, wn = (warp & 1) * 64;
    const int gi = lane >> 2, ti = lane & 3;

    float acc[4][8][4];
#pragma unroll
    for (int i = 0; i < 4; i++)
#pragma unroll
        for (int j = 0; j < 8; j++)
#pragma unroll
            for (int c = 0; c < 4; c++) acc[i][j][c] = 0.f;

    const char* Ab = (const char*)A;
    const char* Bb = (const char*)WT;

#define GSTAGE(S, CH)                                                         \
    {                                                                         \
        char* sb_ = gsm + (S) * GSTGB;                                        \
        _Pragma("unroll")                                                     \
        for (int u = 0; u < 4; u++) {                                         \
            int off = u * 2048 + tid * 16;                                    \
            int r = off >> 6, cb = off & 63;                                  \
            int gr = bm + r; if (gr > SEQ - 1) gr = SEQ - 1;                  \
            cpa16(sb_ + r * 80 + cb, Ab + (size_t)gr * 3072 + (CH) * 64 + cb);\
        }                                                                     \
        _Pragma("unroll")                                                     \
        for (int u = 0; u < 4; u++) {                                         \
            int off = u * 2048 + tid * 16;                                    \
            int r = off >> 6, cb = off & 63;                                  \
            cpa16(sb_ + GSTA + r * 80 + cb,                                   \
                  Bb + (size_t)(bn + r) * 3072 + (CH) * 64 + cb);             \
        }                                                                     \
        asm volatile("cp.async.commit_group;" ::: "memory");                  \
    }

    GSTAGE(0, 0)
    GSTAGE(1, 1)

    for (int ch = 0; ch < NKT; ch++) {
        if (ch == NKT - 1) asm volatile("cp.async.wait_group 0;" ::: "memory");
        else               asm volatile("cp.async.wait_group 1;" ::: "memory");
        __syncthreads();
        // issue prefetch BEFORE compute: buffer (ch+2)%3 == (ch-1)%3, done
        if (ch + 2 < NKT) {
            const int sn = (ch + 2) % 3;
            GSTAGE(sn, ch + 2)
        }

        const __half* As = (const __half*)(gsm + (ch % 3) * GSTGB);
        const __half* Bs = (const __half*)(gsm + (ch % 3) * GSTGB + GSTA);
#pragma unroll
        for (int ks = 0; ks < 2; ks++) {
            const int kk = ks * 16;
            unsigned a[4][4], b[4][4];
#pragma unroll
            for (int mt = 0; mt < 4; mt++)
                ldm4(a[mt], &As[(wm + 16 * mt + (lane & 15)) * GAS
                                + kk + 8 * (lane >> 4)]);
#pragma unroll
            for (int ntp = 0; ntp < 4; ntp++)
                ldm4(b[ntp], &Bs[(wn + 16 * ntp + (lane & 7) + 8 * ((lane >> 4) & 1)) * GAS
                                 + kk + 8 * ((lane >> 3) & 1)]);
#pragma unroll
            for (int mt = 0; mt < 4; mt++)
#pragma unroll
                for (int ntp = 0; ntp < 4; ntp++) {
                    mma16(acc[mt][2 * ntp],     a[mt], &b[ntp][0]);
                    mma16(acc[mt][2 * ntp + 1], a[mt], &b[ntp][2]);
                }
        }
    }
#undef GSTAGE

    // ---- epilogue (unchanged, proven) ----
    if (MODE == 0) {
#pragma unroll
        for (int mt = 0; mt < 4; mt++)
#pragma unroll
            for (int nt = 0; nt < 8; nt++) {
                int gr = bm + wm + 16 * mt + gi;
                int col = bn + wn + 8 * nt + 2 * ti;
                float2 bv = *(const float2*)&b0[col];
                if (gr < SEQ) {
                    float2 rr = { acc[mt][nt][0] + bv.x, acc[mt][nt][1] + bv.y };
                    *(float2*)(o0 + (size_t)gr * DIMF + col) = rr;
                }
                if (gr + 8 < SEQ) {
                    float2 rr = { acc[mt][nt][2] + bv.x, acc[mt][nt][3] + bv.y };
                    *(float2*)(o0 + (size_t)(gr + 8) * DIMF + col) = rr;
                }
            }
    } else {
        const int region = bn < DIMF ? 0 : bn < 2 * DIMF ? 1 : 2;
        const float* bp = region == 0 ? b0 + bn : region == 1 ? b1 + (bn - DIMF)
                                                              : b2 + (bn - 2 * DIMF);
#pragma unroll
        for (int mt = 0; mt < 4; mt++)
#pragma unroll
            for (int nt = 0; nt < 8; nt++) {
                int gr = bm + wm + 16 * mt + gi;
                int l = wn + 8 * nt + 2 * ti;
                float2 bv = *(const float2*)&bp[l];
                float v00 = acc[mt][nt][0] + bv.x, v01 = acc[mt][nt][1] + bv.y;
                float v10 = acc[mt][nt][2] + bv.x, v11 = acc[mt][nt][3] + bv.y;
                if (region == 0) {
                    int col = bn + l;
                    if (gr < SEQ)     *(float2*)(o0 + (size_t)gr * DIMF + col)       = make_float2(v00, v01);
                    if (gr + 8 < SEQ) *(float2*)(o0 + (size_t)(gr + 8) * DIMF + col) = make_float2(v10, v11);
                } else if (region == 1) {
                    int col = bn - DIMF + l;
                    if (gr < SEQ)     *(float2*)(o1 + (size_t)gr * DIMF + col)       = make_float2(v00, v01);
                    if (gr + 8 < SEQ) *(float2*)(o1 + (size_t)(gr + 8) * DIMF + col) = make_float2(v10, v11);
                } else {
                    int vcol = bn - 2 * DIMF + l;
                    int hh = vcol >> 7, d = vcol & 127;
                    if (gr < SEQ)
                        *(__half2*)(o2 + ((size_t)hh * LKV + 3120 + gr) * HD + d) =
                            __floats2half2_rn(v00, v01);
                    if (gr + 8 < SEQ)
                        *(__half2*)(o2 + ((size_t)hh * LKV + 3120 + gr + 8) * HD + d) =
                            __floats2half2_rn(v10, v11);
                }
            }
    }
}

// ---------------------------------------------------------------------------
// Flash attention: q-tile 128, 256 threads (8 warps) -- halves KV traffic,
// single balanced wave (156 blocks). Per-warp mainloop identical to r13.
// ---------------------------------------------------------------------------
#define KVS 136
#define TILEB (64 * KVS)
__global__ __launch_bounds__(256) void attn_h(
    const __half* __restrict__ qh, const __half* __restrict__ kh,
    const __half* __restrict__ vh, __half* __restrict__ oh)
{
    extern __shared__ __half sm[];
    __half* Ks = sm;
    __half* Vs = sm + 2 * TILEB;

    const int h = blockIdx.y, q0 = blockIdx.x * 128;
    const int tid = threadIdx.x, lane = tid & 31, warp = tid >> 5;
    const int gi = lane >> 2, ti = lane & 3;

    const char* kbase = (const char*)(kh + (size_t)h * LKV * HD);
    const char* vbase = (const char*)(vh + (size_t)h * LKV * HD);

    if (tid < 128) {
        uint4 ones = { 0x00003C00u, 0u, 0u, 0u };
        *(uint4*)&Vs[tid * KVS + 128] = ones;
    }

    unsigned qf[8][4];
    {
        int r0 = q0 + warp * 16 + gi, r1 = r0 + 8;
        const __half* p0 = qh + ((size_t)h * SEQ + r0) * HD;
        const __half* p1 = qh + ((size_t)h * SEQ + r1) * HD;
        bool ok0 = r0 < SEQ, ok1 = r1 < SEQ;
#pragma unroll
        for (int kt = 0; kt < 8; kt++) {
            int c = 16 * kt + 2 * ti;
            qf[kt][0] = ok0 ? *(const unsigned*)(p0 + c)     : 0u;
            qf[kt][2] = ok0 ? *(const unsigned*)(p0 + c + 8) : 0u;
            qf[kt][1] = ok1 ? *(const unsigned*)(p1 + c)     : 0u;
            qf[kt][3] = ok1 ? *(const unsigned*)(p1 + c + 8) : 0u;
        }
    }

    float m0v = -1e30f, m1v = -1e30f;
    float o[16][4];
    float lacc[4] = { 0.f, 0.f, 0.f, 0.f };
#pragma unroll
    for (int i = 0; i < 16; i++)
#pragma unroll
        for (int c = 0; c < 4; c++) o[i][c] = 0.f;

    const int NT = (LKV + 63) / 64;

// coalesced KV staging (256 threads: u<4 covers 64 rows x 256B)
#define KVSTAGE(kd, vd, JBASE)                                                \
    {                                                                         \
        _Pragma("unroll")                                                     \
        for (int u = 0; u < 4; u++) {                                         \
            int off = u * 4096 + tid * 16;                                    \
            int r = off >> 8, cb = off & 255;                                 \
            int j = (JBASE) + r; if (j > LKV - 1) j = LKV - 1;                \
            cpa16((char*)(kd) + r * 272 + cb, kbase + (size_t)j * 256 + cb);  \
            cpa16((char*)(vd) + r * 272 + cb, vbase + (size_t)j * 256 + cb);  \
        }                                                                     \
        asm volatile("cp.async.commit_group;" ::: "memory");                  \
    }

    KVSTAGE(Ks, Vs, 0)

    for (int t = 0; t < NT; t++) {
        const int buf = t & 1;
        if (t + 1 < NT) {
            const int nb = (t + 1) & 1;
            KVSTAGE(Ks + nb * TILEB, Vs + nb * TILEB, (t + 1) * 64)
            asm volatile("cp.async.wait_group 1;" ::: "memory");
        } else {
            asm volatile("cp.async.wait_group 0;" ::: "memory");
        }
        __syncthreads();

        const __half* Kb = Ks + buf * TILEB;
        const __half* Vb = Vs + buf * TILEB;
        const int kv0 = t * 64;

        float s[8][4];
#pragma unroll
        for (int nt = 0; nt < 8; nt++)
#pragma unroll
            for (int c = 0; c < 4; c++) s[nt][c] = 0.f;
#pragma unroll
        for (int kt = 0; kt < 8; kt++) {
            const int kk = 16 * kt;
#pragma unroll
            for (int ntp = 0; ntp < 4; ntp++) {
                unsigned b[4];
                ldm4(b, &Kb[(16 * ntp + (lane & 7) + 8 * ((lane >> 4) & 1)) * KVS
                            + kk + 8 * ((lane >> 3) & 1)]);
                mma16(s[2 * ntp],     qf[kt], &b[0]);
                mma16(s[2 * ntp + 1], qf[kt], &b[2]);
            }
        }

        if (kv0 + 64 > LKV) {
#pragma unroll
            for (int nt = 0; nt < 8; nt++) {
                int col = kv0 + 8 * nt + 2 * ti;
                if (col >= LKV)     { s[nt][0] = -1e30f; s[nt][2] = -1e30f; }
                if (col + 1 >= LKV) { s[nt][1] = -1e30f; s[nt][3] = -1e30f; }
            }
        }

        float mx0 = -1e30f, mx1 = -1e30f;
#pragma unroll
        for (int nt = 0; nt < 8; nt++) {
            mx0 = fmaxf(mx0, fmaxf(s[nt][0], s[nt][1]));
            mx1 = fmaxf(mx1, fmaxf(s[nt][2], s[nt][3]));
        }
        mx0 = fmaxf(mx0, __shfl_xor_sync(0xffffffffu, mx0, 1));
        mx0 = fmaxf(mx0, __shfl_xor_sync(0xffffffffu, mx0, 2));
        mx1 = fmaxf(mx1, __shfl_xor_sync(0xffffffffu, mx1, 1));
        mx1 = fmaxf(mx1, __shfl_xor_sync(0xffffffffu, mx1, 2));
        float mn0 = fmaxf(m0v, mx0), mn1 = fmaxf(m1v, mx1);
        bool grew = (mn0 != m0v) || (mn1 != m1v);
        if (__any_sync(0xffffffffu, grew)) {
            float al0 = exp2f(m0v - mn0), al1 = exp2f(m1v - mn1);
#pragma unroll
            for (int nt = 0; nt < 16; nt++) {
                o[nt][0] *= al0; o[nt][1] *= al0;
                o[nt][2] *= al1; o[nt][3] *= al1;
            }
            lacc[0] *= al0; lacc[1] *= al0; lacc[2] *= al1; lacc[3] *= al1;
        }
        m0v = mn0; m1v = mn1;

        unsigned pf[4][4];
#pragma unroll
        for (int j = 0; j < 4; j++) {
            pf[j][0] = ex2h2(pk2(s[2 * j][0] - mn0,     s[2 * j][1] - mn0));
            pf[j][1] = ex2h2(pk2(s[2 * j][2] - mn1,     s[2 * j][3] - mn1));
            pf[j][2] = ex2h2(pk2(s[2 * j + 1][0] - mn0, s[2 * j + 1][1] - mn0));
            pf[j][3] = ex2h2(pk2(s[2 * j + 1][2] - mn1, s[2 * j + 1][3] - mn1));
        }

#pragma unroll
        for (int j = 0; j < 4; j++) {
            const int vrow = (16 * j + (lane & 7) + 8 * ((lane >> 3) & 1)) * KVS;
#pragma unroll
            for (int ntp = 0; ntp < 8; ntp++) {
                unsigned b[4];
                ldm4t(b, &Vb[vrow + 16 * ntp + 8 * ((lane >> 4) & 1)]);
                mma16(o[2 * ntp],     pf[j], &b[0]);
                mma16(o[2 * ntp + 1], pf[j], &b[2]);
            }
            unsigned lb[2];
            ldm2t(lb, &Vb[vrow + 128]);
            mma16(lacc, pf[j], lb);
        }
        __syncthreads();
    }
#undef KVSTAGE

    {
        float l0 = __shfl_sync(0xffffffffu, lacc[0], lane & 28);
        float l1 = __shfl_sync(0xffffffffu, lacc[2], lane & 28);
        int r0 = q0 + warp * 16 + gi, r1 = r0 + 8;
        float i0 = 1.f / l0, i1 = 1.f / l1;
#pragma unroll
        for (int nt = 0; nt < 16; nt++) {
            int c = h * HD + 8 * nt + 2 * ti;
            if (r0 < SEQ)
                *(__half2*)(oh + (size_t)r0 * DIMF + c) =
                    __floats2half2_rn(o[nt][0] * i0, o[nt][1] * i0);
            if (r1 < SEQ)
                *(__half2*)(oh + (size_t)r1 * DIMF + c) =
                    __floats2half2_rn(o[nt][2] * i1, o[nt][3] * i1);
        }
    }
}

// ---------------------------------------------------------------------------
extern "C" void kernel_launch(void* const* d_in, const int* in_sizes, int n_in,
                              void* d_out, int out_size)
{
    (void)in_sizes; (void)n_in; (void)out_size;
    const float* x   = (const float*)d_in[0];
    const float* ck  = (const float*)d_in[1];
    const float* cv  = (const float*)d_in[2];
    const float* fre = (const float*)d_in[3];
    const float* fim = (const float*)d_in[4];
    const float* wq  = (const float*)d_in[5];
    const float* bq  = (const float*)d_in[6];
    const float* wk  = (const float*)d_in[7];
    const float* bk  = (const float*)d_in[8];
    const float* wv  = (const float*)d_in[9];
    const float* bv  = (const float*)d_in[10];
    const float* wo  = (const float*)d_in[11];
    const float* bo  = (const float*)d_in[12];
    const float* gq  = (const float*)d_in[13];
    const float* gk  = (const float*)d_in[14];
    float* out = (float*)d_out;

    float *q, *k;
    __half *xh, *wt, *wot, *qh, *kh, *vh, *oh;
    cudaGetSymbolAddress((void**)&q, g_q);
    cudaGetSymbolAddress((void**)&k, g_k);
    cudaGetSymbolAddress((void**)&xh, g_xh);
    cudaGetSymbolAddress((void**)&wt, g_wt);
    cudaGetSymbolAddress((void**)&wot, g_wot);
    cudaGetSymbolAddress((void**)&qh, g_qh);
    cudaGetSymbolAddress((void**)&kh, g_kh);
    cudaGetSymbolAddress((void**)&vh, g_vh);
    cudaGetSymbolAddress((void**)&oh, g_oh);

    const int gemm_smem = 3 * GSTGB;                        // 61440
    const int attn_smem = 4 * TILEB * (int)sizeof(__half);  // 69632
    cudaFuncSetAttribute((const void*)gemm_h<1>,
                         cudaFuncAttributeMaxDynamicSharedMemorySize, gemm_smem);
    cudaFuncSetAttribute((const void*)gemm_h<0>,
                         cudaFuncAttributeMaxDynamicSharedMemorySize, gemm_smem);
    cudaFuncSetAttribute((const void*)attn_h,
                         cudaFuncAttributeMaxDynamicSharedMemorySize, attn_smem);

    const int NX = SEQ * DIMF;
    // order: attn_h is launch #6 (ncu -s 5 -c 1)
    f2h<<<(NX / 8 + 255) / 256, 256>>>(x, xh, NX);                        // 1
    wtrans<<<dim3(144, 48), dim3(32, 8)>>>(wq, wk, wv, wt);               // 2
    cacheconv<<<(3120 * NH * 16 + 255) / 256, 256>>>(ck, cv, kh, vh);     // 3
    gemm_h<1><<<dim3(13, 36), 128, gemm_smem>>>(                          // 4
        xh, wt, bq, bk, bv, q, k, vh);
    rmsrope<<<dim3(SEQ, 2), 256>>>(q, k, gq, gk, fre, fim, qh, kh);       // 5
    attn_h<<<dim3(13, NH), 256, attn_smem>>>(qh, kh, vh, oh);             // 6
    wtrans<<<dim3(48, 48), dim3(32, 8)>>>(wo, wo, wo, wot);               // 7
    gemm_h<0><<<dim3(13, 12), 128, gemm_smem>>>(                          // 8
        oh, wot, bo, nullptr, nullptr, out, nullptr, nullptr);
}

// round 16
// speedup vs baseline: 1.1783x; 1.1783x over previous
#include <cuda_runtime.h>
#include <cuda_fp16.h>

#define DIMF 1536
#define SEQ  1560
#define LKV  4680
#define NH   12
#define HD   128

// ---------------- device-global scratch (allocation-free) ----------------
__device__ float  g_q[SEQ * DIMF];            // fp32 q pre-norm
__device__ float  g_k[SEQ * DIMF];            // fp32 k pre-norm
__device__ __half g_xh[SEQ * DIMF];           // fp16 x
__device__ __half g_wt[3 * DIMF * DIMF];      // fp16 W^T qkv: [n 4608][k 1536]
__device__ __half g_wot[DIMF * DIMF];         // fp16 Wo^T: [n][k]
__device__ __half g_qh[NH * SEQ * HD];        // fp16 q per-head (RoPE'd, prescaled)
__device__ __half g_kh[NH * LKV * HD];        // fp16 logical K per-head
__device__ __half g_vh[NH * LKV * HD];        // fp16 logical V per-head
__device__ __half g_oh[SEQ * DIMF];           // fp16 attention output

__device__ __forceinline__ unsigned pk2(float a, float b) {
    __half2 h = __floats2half2_rn(a, b);
    return *reinterpret_cast<unsigned*>(&h);
}
__device__ __forceinline__ unsigned ex2h2(unsigned x) {
    unsigned r; asm("ex2.approx.f16x2 %0, %1;" : "=r"(r) : "r"(x)); return r;
}
__device__ __forceinline__ uint4 cvt8(float4 a, float4 b) {
    uint4 u;
    u.x = pk2(a.x, a.y); u.y = pk2(a.z, a.w);
    u.z = pk2(b.x, b.y); u.w = pk2(b.z, b.w);
    return u;
}
__device__ __forceinline__ void mma16(float* d, const unsigned* a, const unsigned* b) {
    asm volatile(
        "mma.sync.aligned.m16n8k16.row.col.f32.f16.f16.f32 "
        "{%0,%1,%2,%3},{%4,%5,%6,%7},{%8,%9},{%0,%1,%2,%3};"
        : "+f"(d[0]), "+f"(d[1]), "+f"(d[2]), "+f"(d[3])
        : "r"(a[0]), "r"(a[1]), "r"(a[2]), "r"(a[3]), "r"(b[0]), "r"(b[1]));
}
__device__ __forceinline__ void ldm4(unsigned* r, const void* p) {
    unsigned a = (unsigned)__cvta_generic_to_shared(p);
    asm volatile("ldmatrix.sync.aligned.m8n8.x4.shared.b16 {%0,%1,%2,%3},[%4];"
                 : "=r"(r[0]), "=r"(r[1]), "=r"(r[2]), "=r"(r[3]) : "r"(a));
}
__device__ __forceinline__ void ldm4t(unsigned* r, const void* p) {
    unsigned a = (unsigned)__cvta_generic_to_shared(p);
    asm volatile("ldmatrix.sync.aligned.m8n8.x4.trans.shared.b16 {%0,%1,%2,%3},[%4];"
                 : "=r"(r[0]), "=r"(r[1]), "=r"(r[2]), "=r"(r[3]) : "r"(a));
}
__device__ __forceinline__ void ldm2t(unsigned* r, const void* p) {
    unsigned a = (unsigned)__cvta_generic_to_shared(p);
    asm volatile("ldmatrix.sync.aligned.m8n8.x2.trans.shared.b16 {%0,%1},[%2];"
                 : "=r"(r[0]), "=r"(r[1]) : "r"(a));
}
__device__ __forceinline__ void cpa16(void* dst, const void* src) {
    unsigned d = (unsigned)__cvta_generic_to_shared(dst);
    asm volatile("cp.async.cg.shared.global [%0], [%1], 16;" :: "r"(d), "l"(src));
}

// ---------------------------------------------------------------------------
// fp32 -> fp16 bulk convert
// ---------------------------------------------------------------------------
__global__ void f2h(const float* __restrict__ in, __half* __restrict__ out, int n) {
    int i = (blockIdx.x * blockDim.x + threadIdx.x) * 8;
    if (i < n) {
        float4 a = *(const float4*)(in + i);
        float4 b = *(const float4*)(in + i + 4);
        *(uint4*)(out + i) = cvt8(a, b);
    }
}

// ---------------------------------------------------------------------------
// W [k][n] fp32 -> W^T [n][k] fp16, tiled transpose
// ---------------------------------------------------------------------------
__global__ __launch_bounds__(256) void wtrans(
    const float* __restrict__ s0, const float* __restrict__ s1,
    const float* __restrict__ s2, __half* __restrict__ wT)
{
    __shared__ float t[32][33];
    int bn = blockIdx.x * 32, bk = blockIdx.y * 32;
    int region = bn / DIMF;
    const float* src = region == 0 ? s0 : region == 1 ? s1 : s2;
    int ln = bn - region * DIMF;
    int tx = threadIdx.x, ty = threadIdx.y;
#pragma unroll
    for (int i = ty; i < 32; i += 8)
        t[i][tx] = src[(size_t)(bk + i) * DIMF + ln + tx];
    __syncthreads();
#pragma unroll
    for (int i = ty; i < 32; i += 8)
        wT[(size_t)(bn + i) * DIMF + bk + tx] = __float2half(t[tx][i]);
}

// ---------------------------------------------------------------------------
// cache rows -> per-head contiguous fp16 logical KV
// ---------------------------------------------------------------------------
__global__ __launch_bounds__(256) void cacheconv(
    const float* __restrict__ ck, const float* __restrict__ cv,
    __half* __restrict__ kh, __half* __restrict__ vh)
{
    int idx = blockIdx.x * 256 + threadIdx.x;
    if (idx >= 3120 * NH * 16) return;
    int d8 = (idx & 15) * 8;
    int jh = idx >> 4;
    int h = jh % NH;
    int j = jh / NH;
    int jj = j < 1560 ? j : j + 1560;
    size_t src = ((size_t)jj * NH + h) * HD + d8;
    size_t dst = ((size_t)h * LKV + j) * HD + d8;
    float4 a0 = *(const float4*)(ck + src);
    float4 a1 = *(const float4*)(ck + src + 4);
    *(uint4*)(kh + dst) = cvt8(a0, a1);
    float4 b0 = *(const float4*)(cv + src);
    float4 b1 = *(const float4*)(cv + src + 4);
    *(uint4*)(vh + dst) = cvt8(b0, b1);
}

// ---------------------------------------------------------------------------
// RMSNorm + RoPE (unchanged)
// ---------------------------------------------------------------------------
__global__ __launch_bounds__(256) void rmsrope(
    const float* __restrict__ qbuf, const float* __restrict__ kbuf,
    const float* __restrict__ gq, const float* __restrict__ gk,
    const float* __restrict__ fre, const float* __restrict__ fim,
    __half* __restrict__ qh, __half* __restrict__ kh)
{
    const int t = blockIdx.x;
    const bool isq = blockIdx.y == 0;
    const float* row = (isq ? qbuf : kbuf) + (size_t)t * DIMF;
    const float* g = isq ? gq : gk;
    const int tid = threadIdx.x;

    float ss = 0.f;
#pragma unroll
    for (int u = 0; u < 6; u++) { float v = row[tid + u * 256]; ss += v * v; }
#pragma unroll
    for (int off = 16; off; off >>= 1) ss += __shfl_xor_sync(0xffffffffu, ss, off);
    __shared__ float red[8];
    if ((tid & 31) == 0) red[tid >> 5] = ss;
    __syncthreads();
    float tot = red[0] + red[1] + red[2] + red[3] + red[4] + red[5] + red[6] + red[7];
    float r = rsqrtf(tot * (1.f / 1536.f) + 1e-6f);
    const float sc = isq ? 0.08838834764831845f * 1.4426950408889634f : 1.0f;

    const int wi = t % 52;
    const int hi = t / 52;
#pragma unroll
    for (int u = 0; u < 3; u++) {
        int p = tid + u * 256;
        int hh = p >> 6, c = p & 63;
        int d0 = hh * 128 + 2 * c;
        int frow = (c < 22) ? 3 : (c < 43) ? hi : wi;
        float cr = fre[frow * 64 + c], ci = fim[frow * 64 + c];
        float v0 = row[d0] * r * g[d0];
        float v1 = row[d0 + 1] * r * g[d0 + 1];
        float y0 = (v0 * cr - v1 * ci) * sc;
        float y1 = (v0 * ci + v1 * cr) * sc;
        __half* dst = isq ? qh + ((size_t)hh * SEQ + t) * HD + 2 * c
                          : kh + ((size_t)hh * LKV + 3120 + t) * HD + 2 * c;
        *(__half2*)dst = __floats2half2_rn(y0, y1);
    }
}

// ---------------------------------------------------------------------------
// GEMM (round-13 proven): BM=BN=128, BK=64, 128 threads, warp tile 64x64,
// 2-stage coalesced cp.async, 3 blocks/SM.
// ---------------------------------------------------------------------------
#define GAS 72                     // halfs per staged row (64 + 8 pad)
#define ASTGB (128 * GAS * 2)      // bytes of A region per stage
#define STAGEB (2 * ASTGB)         // A + B
#define NKT 24                     // 1536 / 64

template <int MODE>
__global__ __launch_bounds__(128, 3) void gemm_h(
    const __half* __restrict__ A, const __half* __restrict__ WT,
    const float* __restrict__ b0, const float* __restrict__ b1,
    const float* __restrict__ b2,
    float* __restrict__ o0, float* __restrict__ o1, __half* __restrict__ o2)
{
    extern __shared__ char gsm[];
    const int bm = blockIdx.x * 128, bn = blockIdx.y * 128;
    const int tid = threadIdx.x, lane = tid & 31, warp = tid >> 5;
    const int wm = (warp >> 1) * 64, wn = (warp & 1) * 64;
    const int gi = lane >> 2, ti = lane & 3;

    float acc[4][8][4];
#pragma unroll
    for (int i = 0; i < 4; i++)
#pragma unroll
        for (int j = 0; j < 8; j++)
#pragma unroll
            for (int c = 0; c < 4; c++) acc[i][j][c] = 0.f;

    const char* Ab = (const char*)A;
    const char* Bb = (const char*)WT;

#define GSTAGE(S, CH)                                                         \
    {                                                                         \
        char* sb_ = gsm + (S) * STAGEB;                                       \
        _Pragma("unroll")                                                     \
        for (int u = 0; u < 8; u++) {                                         \
            int off = u * 2048 + tid * 16;                                    \
            int r = off >> 7, cb = off & 127;                                 \
            int gr = bm + r; if (gr > SEQ - 1) gr = SEQ - 1;                  \
            cpa16(sb_ + r * 144 + cb, Ab + (size_t)gr * 3072 + (CH) * 128 + cb); \
        }                                                                     \
        _Pragma("unroll")                                                     \
        for (int u = 0; u < 8; u++) {                                         \
            int off = u * 2048 + tid * 16;                                    \
            int r = off >> 7, cb = off & 127;                                 \
            cpa16(sb_ + ASTGB + r * 144 + cb,                                 \
                  Bb + (size_t)(bn + r) * 3072 + (CH) * 128 + cb);            \
        }                                                                     \
        asm volatile("cp.async.commit_group;" ::: "memory");                  \
    }

    GSTAGE(0, 0)
    GSTAGE(1, 1)

    for (int ch = 0; ch < NKT; ch++) {
        const int S = ch & 1;
        if (ch == NKT - 1) asm volatile("cp.async.wait_group 0;" ::: "memory");
        else               asm volatile("cp.async.wait_group 1;" ::: "memory");
        __syncthreads();

        const __half* As = (const __half*)(gsm + S * STAGEB);
        const __half* Bs = (const __half*)(gsm + S * STAGEB + ASTGB);
#pragma unroll
        for (int ks = 0; ks < 4; ks++) {
            const int kk = ks * 16;
            unsigned a[4][4], b[4][4];
#pragma unroll
            for (int mt = 0; mt < 4; mt++)
                ldm4(a[mt], &As[(wm + 16 * mt + (lane & 15)) * GAS
                                + kk + 8 * (lane >> 4)]);
#pragma unroll
            for (int ntp = 0; ntp < 4; ntp++)
                ldm4(b[ntp], &Bs[(wn + 16 * ntp + (lane & 7) + 8 * ((lane >> 4) & 1)) * GAS
                                 + kk + 8 * ((lane >> 3) & 1)]);
#pragma unroll
            for (int mt = 0; mt < 4; mt++)
#pragma unroll
                for (int ntp = 0; ntp < 4; ntp++) {
                    mma16(acc[mt][2 * ntp],     a[mt], &b[ntp][0]);
                    mma16(acc[mt][2 * ntp + 1], a[mt], &b[ntp][2]);
                }
        }
        __syncthreads();
        if (ch + 2 < NKT) GSTAGE(S, ch + 2)
    }
#undef GSTAGE

    // ---- epilogue (unchanged, proven) ----
    if (MODE == 0) {
#pragma unroll
        for (int mt = 0; mt < 4; mt++)
#pragma unroll
            for (int nt = 0; nt < 8; nt++) {
                int gr = bm + wm + 16 * mt + gi;
                int col = bn + wn + 8 * nt + 2 * ti;
                float2 bv = *(const float2*)&b0[col];
                if (gr < SEQ) {
                    float2 rr = { acc[mt][nt][0] + bv.x, acc[mt][nt][1] + bv.y };
                    *(float2*)(o0 + (size_t)gr * DIMF + col) = rr;
                }
                if (gr + 8 < SEQ) {
                    float2 rr = { acc[mt][nt][2] + bv.x, acc[mt][nt][3] + bv.y };
                    *(float2*)(o0 + (size_t)(gr + 8) * DIMF + col) = rr;
                }
            }
    } else {
        const int region = bn < DIMF ? 0 : bn < 2 * DIMF ? 1 : 2;
        const float* bp = region == 0 ? b0 + bn : region == 1 ? b1 + (bn - DIMF)
                                                              : b2 + (bn - 2 * DIMF);
#pragma unroll
        for (int mt = 0; mt < 4; mt++)
#pragma unroll
            for (int nt = 0; nt < 8; nt++) {
                int gr = bm + wm + 16 * mt + gi;
                int l = wn + 8 * nt + 2 * ti;
                float2 bv = *(const float2*)&bp[l];
                float v00 = acc[mt][nt][0] + bv.x, v01 = acc[mt][nt][1] + bv.y;
                float v10 = acc[mt][nt][2] + bv.x, v11 = acc[mt][nt][3] + bv.y;
                if (region == 0) {
                    int col = bn + l;
                    if (gr < SEQ)     *(float2*)(o0 + (size_t)gr * DIMF + col)       = make_float2(v00, v01);
                    if (gr + 8 < SEQ) *(float2*)(o0 + (size_t)(gr + 8) * DIMF + col) = make_float2(v10, v11);
                } else if (region == 1) {
                    int col = bn - DIMF + l;
                    if (gr < SEQ)     *(float2*)(o1 + (size_t)gr * DIMF + col)       = make_float2(v00, v01);
                    if (gr + 8 < SEQ) *(float2*)(o1 + (size_t)(gr + 8) * DIMF + col) = make_float2(v10, v11);
                } else {
                    int vcol = bn - 2 * DIMF + l;
                    int hh = vcol >> 7, d = vcol & 127;
                    if (gr < SEQ)
                        *(__half2*)(o2 + ((size_t)hh * LKV + 3120 + gr) * HD + d) =
                            __floats2half2_rn(v00, v01);
                    if (gr + 8 < SEQ)
                        *(__half2*)(o2 + ((size_t)hh * LKV + 3120 + gr + 8) * HD + d) =
                            __floats2half2_rn(v10, v11);
                }
            }
    }
}

// ---------------------------------------------------------------------------
// Flash attention: q-tile 96, 192 threads (6 warps), 2 blocks/SM pinned.
// 204 blocks <= 296 slots = one wave; KV re-reads 25 -> 17. Per-warp mainloop
// identical to proven round-13 code.
// ---------------------------------------------------------------------------
#define KVS 136
#define TILEB (64 * KVS)
__global__ __launch_bounds__(192, 2) void attn_h(
    const __half* __restrict__ qh, const __half* __restrict__ kh,
    const __half* __restrict__ vh, __half* __restrict__ oh)
{
    extern __shared__ __half sm[];
    __half* Ks = sm;
    __half* Vs = sm + 2 * TILEB;

    const int h = blockIdx.y, q0 = blockIdx.x * 96;
    const int tid = threadIdx.x, lane = tid & 31, warp = tid >> 5;
    const int gi = lane >> 2, ti = lane & 3;

    const char* kbase = (const char*)(kh + (size_t)h * LKV * HD);
    const char* vbase = (const char*)(vh + (size_t)h * LKV * HD);

    if (tid < 128) {
        uint4 ones = { 0x00003C00u, 0u, 0u, 0u };
        *(uint4*)&Vs[tid * KVS + 128] = ones;
    }

    unsigned qf[8][4];
    {
        int r0 = q0 + warp * 16 + gi, r1 = r0 + 8;
        const __half* p0 = qh + ((size_t)h * SEQ + r0) * HD;
        const __half* p1 = qh + ((size_t)h * SEQ + r1) * HD;
        bool ok0 = r0 < SEQ, ok1 = r1 < SEQ;
#pragma unroll
        for (int kt = 0; kt < 8; kt++) {
            int c = 16 * kt + 2 * ti;
            qf[kt][0] = ok0 ? *(const unsigned*)(p0 + c)     : 0u;
            qf[kt][2] = ok0 ? *(const unsigned*)(p0 + c + 8) : 0u;
            qf[kt][1] = ok1 ? *(const unsigned*)(p1 + c)     : 0u;
            qf[kt][3] = ok1 ? *(const unsigned*)(p1 + c + 8) : 0u;
        }
    }

    float m0v = -1e30f, m1v = -1e30f;
    float o[16][4];
    float lacc[4] = { 0.f, 0.f, 0.f, 0.f };
#pragma unroll
    for (int i = 0; i < 16; i++)
#pragma unroll
        for (int c = 0; c < 4; c++) o[i][c] = 0.f;

    const int NT = (LKV + 63) / 64;

// coalesced KV staging with 192 threads (6 passes, last partially masked)
#define KVSTAGE(kd, vd, JBASE)                                                \
    {                                                                         \
        _Pragma("unroll")                                                     \
        for (int u = 0; u < 6; u++) {                                         \
            int off = u * 3072 + tid * 16;                                    \
            if (off < 16384) {                                                \
                int r = off >> 8, cb = off & 255;                             \
                int j = (JBASE) + r; if (j > LKV - 1) j = LKV - 1;            \
                cpa16((char*)(kd) + r * 272 + cb, kbase + (size_t)j * 256 + cb); \
                cpa16((char*)(vd) + r * 272 + cb, vbase + (size_t)j * 256 + cb); \
            }                                                                 \
        }                                                                     \
        asm volatile("cp.async.commit_group;" ::: "memory");                  \
    }

    KVSTAGE(Ks, Vs, 0)

    for (int t = 0; t < NT; t++) {
        const int buf = t & 1;
        if (t + 1 < NT) {
            const int nb = (t + 1) & 1;
            KVSTAGE(Ks + nb * TILEB, Vs + nb * TILEB, (t + 1) * 64)
            asm volatile("cp.async.wait_group 1;" ::: "memory");
        } else {
            asm volatile("cp.async.wait_group 0;" ::: "memory");
        }
        __syncthreads();

        const __half* Kb = Ks + buf * TILEB;
        const __half* Vb = Vs + buf * TILEB;
        const int kv0 = t * 64;

        float s[8][4];
#pragma unroll
        for (int nt = 0; nt < 8; nt++)
#pragma unroll
            for (int c = 0; c < 4; c++) s[nt][c] = 0.f;
#pragma unroll
        for (int kt = 0; kt < 8; kt++) {
            const int kk = 16 * kt;
#pragma unroll
            for (int ntp = 0; ntp < 4; ntp++) {
                unsigned b[4];
                ldm4(b, &Kb[(16 * ntp + (lane & 7) + 8 * ((lane >> 4) & 1)) * KVS
                            + kk + 8 * ((lane >> 3) & 1)]);
                mma16(s[2 * ntp],     qf[kt], &b[0]);
                mma16(s[2 * ntp + 1], qf[kt], &b[2]);
            }
        }

        if (kv0 + 64 > LKV) {
#pragma unroll
            for (int nt = 0; nt < 8; nt++) {
                int col = kv0 + 8 * nt + 2 * ti;
                if (col >= LKV)     { s[nt][0] = -1e30f; s[nt][2] = -1e30f; }
                if (col + 1 >= LKV) { s[nt][1] = -1e30f; s[nt][3] = -1e30f; }
            }
        }

        float mx0 = -1e30f, mx1 = -1e30f;
#pragma unroll
        for (int nt = 0; nt < 8; nt++) {
            mx0 = fmaxf(mx0, fmaxf(s[nt][0], s[nt][1]));
            mx1 = fmaxf(mx1, fmaxf(s[nt][2], s[nt][3]));
        }
        mx0 = fmaxf(mx0, __shfl_xor_sync(0xffffffffu, mx0, 1));
        mx0 = fmaxf(mx0, __shfl_xor_sync(0xffffffffu, mx0, 2));
        mx1 = fmaxf(mx1, __shfl_xor_sync(0xffffffffu, mx1, 1));
        mx1 = fmaxf(mx1, __shfl_xor_sync(0xffffffffu, mx1, 2));
        float mn0 = fmaxf(m0v, mx0), mn1 = fmaxf(m1v, mx1);
        bool grew = (mn0 != m0v) || (mn1 != m1v);
        if (__any_sync(0xffffffffu, grew)) {
            float al0 = exp2f(m0v - mn0), al1 = exp2f(m1v - mn1);
#pragma unroll
            for (int nt = 0; nt < 16; nt++) {
                o[nt][0] *= al0; o[nt][1] *= al0;
                o[nt][2] *= al1; o[nt][3] *= al1;
            }
            lacc[0] *= al0; lacc[1] *= al0; lacc[2] *= al1; lacc[3] *= al1;
        }
        m0v = mn0; m1v = mn1;

        unsigned pf[4][4];
#pragma unroll
        for (int j = 0; j < 4; j++) {
            pf[j][0] = ex2h2(pk2(s[2 * j][0] - mn0,     s[2 * j][1] - mn0));
            pf[j][1] = ex2h2(pk2(s[2 * j][2] - mn1,     s[2 * j][3] - mn1));
            pf[j][2] = ex2h2(pk2(s[2 * j + 1][0] - mn0, s[2 * j + 1][1] - mn0));
            pf[j][3] = ex2h2(pk2(s[2 * j + 1][2] - mn1, s[2 * j + 1][3] - mn1));
        }

#pragma unroll
        for (int j = 0; j < 4; j++) {
            const int vrow = (16 * j + (lane & 7) + 8 * ((lane >> 3) & 1)) * KVS;
#pragma unroll
            for (int ntp = 0; ntp < 8; ntp++) {
                unsigned b[4];
                ldm4t(b, &Vb[vrow + 16 * ntp + 8 * ((lane >> 4) & 1)]);
                mma16(o[2 * ntp],     pf[j], &b[0]);
                mma16(o[2 * ntp + 1], pf[j], &b[2]);
            }
            unsigned lb[2];
            ldm2t(lb, &Vb[vrow + 128]);
            mma16(lacc, pf[j], lb);
        }
        __syncthreads();
    }
#undef KVSTAGE

    {
        float l0 = __shfl_sync(0xffffffffu, lacc[0], lane & 28);
        float l1 = __shfl_sync(0xffffffffu, lacc[2], lane & 28);
        int r0 = q0 + warp * 16 + gi, r1 = r0 + 8;
        float i0 = 1.f / l0, i1 = 1.f / l1;
#pragma unroll
        for (int nt = 0; nt < 16; nt++) {
            int c = h * HD + 8 * nt + 2 * ti;
            if (r0 < SEQ)
                *(__half2*)(oh + (size_t)r0 * DIMF + c) =
                    __floats2half2_rn(o[nt][0] * i0, o[nt][1] * i0);
            if (r1 < SEQ)
                *(__half2*)(oh + (size_t)r1 * DIMF + c) =
                    __floats2half2_rn(o[nt][2] * i1, o[nt][3] * i1);
        }
    }
}

// ---------------------------------------------------------------------------
extern "C" void kernel_launch(void* const* d_in, const int* in_sizes, int n_in,
                              void* d_out, int out_size)
{
    (void)in_sizes; (void)n_in; (void)out_size;
    const float* x   = (const float*)d_in[0];
    const float* ck  = (const float*)d_in[1];
    const float* cv  = (const float*)d_in[2];
    const float* fre = (const float*)d_in[3];
    const float* fim = (const float*)d_in[4];
    const float* wq  = (const float*)d_in[5];
    const float* bq  = (const float*)d_in[6];
    const float* wk  = (const float*)d_in[7];
    const float* bk  = (const float*)d_in[8];
    const float* wv  = (const float*)d_in[9];
    const float* bv  = (const float*)d_in[10];
    const float* wo  = (const float*)d_in[11];
    const float* bo  = (const float*)d_in[12];
    const float* gq  = (const float*)d_in[13];
    const float* gk  = (const float*)d_in[14];
    float* out = (float*)d_out;

    float *q, *k;
    __half *xh, *wt, *wot, *qh, *kh, *vh, *oh;
    cudaGetSymbolAddress((void**)&q, g_q);
    cudaGetSymbolAddress((void**)&k, g_k);
    cudaGetSymbolAddress((void**)&xh, g_xh);
    cudaGetSymbolAddress((void**)&wt, g_wt);
    cudaGetSymbolAddress((void**)&wot, g_wot);
    cudaGetSymbolAddress((void**)&qh, g_qh);
    cudaGetSymbolAddress((void**)&kh, g_kh);
    cudaGetSymbolAddress((void**)&vh, g_vh);
    cudaGetSymbolAddress((void**)&oh, g_oh);

    const int gemm_smem = 2 * STAGEB;                       // 73728
    const int attn_smem = 4 * TILEB * (int)sizeof(__half);  // 69632
    cudaFuncSetAttribute((const void*)gemm_h<1>,
                         cudaFuncAttributeMaxDynamicSharedMemorySize, gemm_smem);
    cudaFuncSetAttribute((const void*)gemm_h<0>,
                         cudaFuncAttributeMaxDynamicSharedMemorySize, gemm_smem);
    cudaFuncSetAttribute((const void*)attn_h,
                         cudaFuncAttributeMaxDynamicSharedMemorySize, attn_smem);

    const int NX = SEQ * DIMF;
    // order: attn_h is launch #6 (ncu -s 5 -c 1)
    f2h<<<(NX / 8 + 255) / 256, 256>>>(x, xh, NX);                        // 1
    wtrans<<<dim3(144, 48), dim3(32, 8)>>>(wq, wk, wv, wt);               // 2
    cacheconv<<<(3120 * NH * 16 + 255) / 256, 256>>>(ck, cv, kh, vh);     // 3
    gemm_h<1><<<dim3(13, 36), 128, gemm_smem>>>(                          // 4
        xh, wt, bq, bk, bv, q, k, vh);
    rmsrope<<<dim3(SEQ, 2), 256>>>(q, k, gq, gk, fre, fim, qh, kh);       // 5
    attn_h<<<dim3(17, NH), 192, attn_smem>>>(qh, kh, vh, oh);             // 6
    wtrans<<<dim3(48, 48), dim3(32, 8)>>>(wo, wo, wo, wot);               // 7
    gemm_h<0><<<dim3(13, 12), 128, gemm_smem>>>(                          // 8
        oh, wot, bo, nullptr, nullptr, out, nullptr, nullptr);
}